// round 10
// baseline (speedup 1.0000x reference)
#include <cuda_runtime.h>
#include <cuda_bf16.h>
#include <math.h>
#include <stdint.h>

// Problem constants
#define BSZ   2
#define SEQ   1024
#define DMODEL 4096
#define NH    32
#define NKVH  8
#define HD    128
#define MROWS (BSZ * SEQ)      // 2048
#define QCOLS (NH * HD)        // 4096
#define KCOLS (NKVH * HD)      // 1024

// Scratch (no allocations allowed — device globals)
__device__ float g_Q [(size_t)MROWS * QCOLS];
__device__ float g_K [(size_t)MROWS * KCOLS];
__device__ float g_V [(size_t)MROWS * KCOLS];
__device__ float g_AO[(size_t)MROWS * QCOLS];
__device__ int   g_dummy;

// ---------------------------------------------------------------------------
// Dummy kernel: aligns ncu's -s 5 skip window so the GEMM gets profiled.
// ---------------------------------------------------------------------------
__global__ void warm_kernel(int* d) { if (threadIdx.x == 0) *d = 1; }

// ---------------------------------------------------------------------------
// helpers
// ---------------------------------------------------------------------------
__device__ __forceinline__ void mma16816(float c[4], const uint32_t a[4],
                                         uint32_t b0, uint32_t b1) {
    asm volatile("mma.sync.aligned.m16n8k16.row.col.f32.bf16.bf16.f32 "
                 "{%0,%1,%2,%3}, {%4,%5,%6,%7}, {%8,%9}, {%0,%1,%2,%3};"
                 : "+f"(c[0]), "+f"(c[1]), "+f"(c[2]), "+f"(c[3])
                 : "r"(a[0]), "r"(a[1]), "r"(a[2]), "r"(a[3]), "r"(b0), "r"(b1));
}

// RN split: fp32 pair -> packed bf16x2 hi (RN) + lo (RN of residual).
// Low 16 bits of the packed reg = first argument (lower k index).
__device__ __forceinline__ void split2(float a, float b, uint32_t& hi, uint32_t& lo) {
    asm("cvt.rn.bf16x2.f32 %0, %1, %2;" : "=r"(hi) : "f"(b), "f"(a));
    float ha = __uint_as_float(hi << 16);
    float hb = __uint_as_float(hi & 0xffff0000u);
    float la = a - ha;
    float lb = b - hb;
    asm("cvt.rn.bf16x2.f32 %0, %1, %2;" : "=r"(lo) : "f"(lb), "f"(la));
}

// ---------------------------------------------------------------------------
// Hybrid GEMM: C[M,N] = A[M,K] @ W[K,N] (+bias)
// CTA tile 128x128, BK=16, 512 threads = 16 warps (4/SMSP: 3 FFMA + 1 HMMA).
//   warps 0-11 : fp32 FFMA, rows 0-95   (warp = 32x32, thread = 4x8)
//   warps 12-15: bf16 3-term HMMA, rows 96-127 (warp = 32x32)
// Double-buffered smem (As[k][m]-transposed, Bs[k][n]), register prefetch,
// one __syncthreads per iteration.
// ---------------------------------------------------------------------------
__global__ __launch_bounds__(512)
void sgemm_hybrid(const float* __restrict__ A, const float* __restrict__ W,
                  const float* __restrict__ bias, float* __restrict__ C,
                  int M, int N, int K)
{
    __shared__ __align__(16) float As[2][16][128];   // [buf][k][m]
    __shared__ __align__(16) float Bs[2][16][128];   // [buf][k][n]

    const int t    = threadIdx.x;
    const int lane = t & 31;
    const int w    = t >> 5;
    const int row0 = blockIdx.y * 128;
    const int col0 = blockIdx.x * 128;

    // staging mapping (all 512 threads): one float4 of A, one of B
    const int a_row = t >> 2, a_k4 = t & 3;   // A (a_row, a_k4*4..+3)
    const int b_k   = t >> 5, b_n16 = t & 31; // B (b_k, b_n16*4..+3)
    float4 ra, rb;

    auto LOAD = [&](int kb) {
        ra = *reinterpret_cast<const float4*>(A + (size_t)(row0 + a_row) * K + kb + a_k4 * 4);
        rb = *reinterpret_cast<const float4*>(W + (size_t)(kb + b_k) * N + col0 + b_n16 * 4);
    };
    auto STORE = [&](int buf) {
        As[buf][a_k4 * 4 + 0][a_row] = ra.x;
        As[buf][a_k4 * 4 + 1][a_row] = ra.y;
        As[buf][a_k4 * 4 + 2][a_row] = ra.z;
        As[buf][a_k4 * 4 + 3][a_row] = ra.w;
        *reinterpret_cast<float4*>(&Bs[buf][b_k][b_n16 * 4]) = rb;
    };

    const int niter = K >> 4;

    // per-path registers
    float acc[4][8];                 // FFMA path
    float hc[2][4][4];               // HMMA path
    if (w < 12) {
#pragma unroll
        for (int i = 0; i < 4; i++)
#pragma unroll
            for (int j = 0; j < 8; j++) acc[i][j] = 0.f;
    } else {
#pragma unroll
        for (int mi = 0; mi < 2; mi++)
#pragma unroll
            for (int ni = 0; ni < 4; ni++)
#pragma unroll
                for (int e = 0; e < 4; e++) hc[mi][ni][e] = 0.f;
    }

    // FFMA thread coordinates
    const int rg  = w >> 2, cg = w & 3;               // (only valid w<12)
    const int r0  = rg * 32 + (lane & 7) * 4;
    const int c0l = cg * 32 + (lane >> 3) * 8;
    // HMMA thread coordinates
    const int hc0 = (w - 12) * 32;                    // (only valid w>=12)
    const int fr  = lane >> 2;
    const int c2  = (lane & 3) * 2;

    LOAD(0);
    STORE(0);
    LOAD(16);
    __syncthreads();

    for (int i = 0; i < niter; i++) {
        const int cur = i & 1;

        if (w < 12) {
            // ---------------- FFMA warps: rows 0-95 ----------------
#pragma unroll
            for (int kk = 0; kk < 16; kk++) {
                float4 av  = *reinterpret_cast<const float4*>(&As[cur][kk][r0]);
                float4 bv0 = *reinterpret_cast<const float4*>(&Bs[cur][kk][c0l]);
                float4 bv1 = *reinterpret_cast<const float4*>(&Bs[cur][kk][c0l + 4]);
                float a4[4] = {av.x, av.y, av.z, av.w};
                float b8[8] = {bv0.x, bv0.y, bv0.z, bv0.w, bv1.x, bv1.y, bv1.z, bv1.w};
#pragma unroll
                for (int ii = 0; ii < 4; ii++)
#pragma unroll
                    for (int jj = 0; jj < 8; jj++)
                        acc[ii][jj] += a4[ii] * b8[jj];
            }
        } else {
            // ---------------- HMMA warps: rows 96-127 ----------------
            uint32_t ahi[2][4], alo[2][4], bhi[4][2], blo[4][2];
#pragma unroll
            for (int mi = 0; mi < 2; mi++) {
                const int r = 96 + mi * 16 + fr;
                float v00 = As[cur][c2][r],         v01 = As[cur][c2 + 1][r];
                float v10 = As[cur][c2][r + 8],     v11 = As[cur][c2 + 1][r + 8];
                float v02 = As[cur][c2 + 8][r],     v03 = As[cur][c2 + 9][r];
                float v12 = As[cur][c2 + 8][r + 8], v13 = As[cur][c2 + 9][r + 8];
                split2(v00, v01, ahi[mi][0], alo[mi][0]);
                split2(v10, v11, ahi[mi][1], alo[mi][1]);
                split2(v02, v03, ahi[mi][2], alo[mi][2]);
                split2(v12, v13, ahi[mi][3], alo[mi][3]);
            }
#pragma unroll
            for (int ni = 0; ni < 4; ni++) {
                const int n = hc0 + ni * 8 + fr;
                split2(Bs[cur][c2][n],     Bs[cur][c2 + 1][n], bhi[ni][0], blo[ni][0]);
                split2(Bs[cur][c2 + 8][n], Bs[cur][c2 + 9][n], bhi[ni][1], blo[ni][1]);
            }
#pragma unroll
            for (int mi = 0; mi < 2; mi++)
#pragma unroll
                for (int ni = 0; ni < 4; ni++) {
                    mma16816(hc[mi][ni], ahi[mi], bhi[ni][0], bhi[ni][1]);
                    mma16816(hc[mi][ni], alo[mi], bhi[ni][0], bhi[ni][1]);
                    mma16816(hc[mi][ni], ahi[mi], blo[ni][0], blo[ni][1]);
                }
        }

        if (i + 1 < niter) {
            STORE(cur ^ 1);
            if (i + 2 < niter) LOAD((i + 2) << 4);
            __syncthreads();
        }
    }

    // ---------------- epilogue ----------------
    if (w < 12) {
#pragma unroll
        for (int ii = 0; ii < 4; ii++) {
            int r  = row0 + rg * 32 + (lane & 7) * 4 + ii;
            int cb = col0 + c0l;
            float4 v0 = make_float4(acc[ii][0], acc[ii][1], acc[ii][2], acc[ii][3]);
            float4 v1 = make_float4(acc[ii][4], acc[ii][5], acc[ii][6], acc[ii][7]);
            if (bias) {
                v0.x += bias[cb + 0]; v0.y += bias[cb + 1];
                v0.z += bias[cb + 2]; v0.w += bias[cb + 3];
                v1.x += bias[cb + 4]; v1.y += bias[cb + 5];
                v1.z += bias[cb + 6]; v1.w += bias[cb + 7];
            }
            *reinterpret_cast<float4*>(C + (size_t)r * N + cb)     = v0;
            *reinterpret_cast<float4*>(C + (size_t)r * N + cb + 4) = v1;
        }
    } else {
#pragma unroll
        for (int mi = 0; mi < 2; mi++)
#pragma unroll
            for (int ni = 0; ni < 4; ni++) {
                int r   = row0 + 96 + mi * 16 + fr;
                int col = col0 + hc0 + ni * 8 + c2;
                float bx = bias ? bias[col]     : 0.f;
                float by = bias ? bias[col + 1] : 0.f;
                float2 v0 = make_float2(hc[mi][ni][0] + bx, hc[mi][ni][1] + by);
                float2 v1 = make_float2(hc[mi][ni][2] + bx, hc[mi][ni][3] + by);
                *reinterpret_cast<float2*>(C + (size_t)r * N + col)       = v0;
                *reinterpret_cast<float2*>(C + (size_t)(r + 8) * N + col) = v1;
            }
    }
}

// ---------------------------------------------------------------------------
// RoPE (in-place): buf layout [MROWS][nheads*128].
// ---------------------------------------------------------------------------
__global__ void rope_kernel(float* __restrict__ buf,
                            const int* __restrict__ sidx, int nheads)
{
    int idx = blockIdx.x * blockDim.x + threadIdx.x;
    int total = MROWS * nheads * 64;
    if (idx >= total) return;
    int d   = idx & 63;
    int rem = idx >> 6;
    int h   = rem % nheads;
    int row = rem / nheads;
    int s   = row & (SEQ - 1);

    double pos = (double)sidx[s];
    double ang = pos * exp(-((double)d / 64.0) * 13.815510557964274);
    double sn, cs;
    sincos(ang, &sn, &cs);

    float* p = buf + (size_t)row * (nheads * 128) + h * 128 + d;
    float t1 = p[0];
    float t2 = p[64];
    p[0]  = t1 * (float)cs - t2 * (float)sn;
    p[64] = t2 * (float)cs + t1 * (float)sn;
}

// ---------------------------------------------------------------------------
// Flash attention (fp32, causal). BQ=64, BK=32, 256 threads.
// ---------------------------------------------------------------------------
__global__ __launch_bounds__(256)
void attn_kernel(const float* __restrict__ Q, const float* __restrict__ Kc,
                 const float* __restrict__ Vc, const int* __restrict__ sidx,
                 float* __restrict__ O)
{
    __shared__ float4 Ks[32][32];
    __shared__ float4 Vs[32][32];
    __shared__ int    spos[32];

    const int t   = threadIdx.x;
    const int r   = t >> 2;
    const int sub = t & 3;
    const int b   = blockIdx.z;
    const int h   = blockIdx.y;
    const int q0  = blockIdx.x * 64;
    const int kvh = h >> 2;
    const int sq  = q0 + r;
    const int pos_q = sidx[sq];
    const float scale = 0.08838834764831845f;

    float4 qreg[8];
    {
        const float4* qp = reinterpret_cast<const float4*>(
            Q + (size_t)(b * SEQ + sq) * QCOLS + h * 128 + sub * 32);
#pragma unroll
        for (int c = 0; c < 8; c++) qreg[c] = qp[c];
    }

    float  m = -1e30f, l = 0.f;
    float4 acc[8];
#pragma unroll
    for (int c = 0; c < 8; c++) acc[c] = make_float4(0.f, 0.f, 0.f, 0.f);

    const float* Kbase = Kc + (size_t)b * SEQ * KCOLS + kvh * 128;
    const float* Vbase = Vc + (size_t)b * SEQ * KCOLS + kvh * 128;

    for (int k0 = 0; k0 < q0 + 64; k0 += 32) {
        __syncthreads();
#pragma unroll
        for (int ww = 0; ww < 4; ww++) {
            int f  = ww * 256 + t;
            int j  = f >> 5;
            int i4 = f & 31;
            Ks[j][i4] = *reinterpret_cast<const float4*>(
                Kbase + (size_t)(k0 + j) * KCOLS + i4 * 4);
            Vs[j][i4] = *reinterpret_cast<const float4*>(
                Vbase + (size_t)(k0 + j) * KCOLS + i4 * 4);
        }
        if (t < 32) spos[t] = sidx[k0 + t];
        __syncthreads();

        float sc[32];
        float tmax = -1e30f;
#pragma unroll
        for (int j = 0; j < 32; j++) {
            float s = 0.f;
#pragma unroll
            for (int c0 = 0; c0 < 8; c0++) {
                int c = (c0 + 2 * sub) & 7;
                float4 k4 = Ks[j][sub * 8 + c];
                float4 q4 = qreg[c];
                s += q4.x * k4.x + q4.y * k4.y + q4.z * k4.z + q4.w * k4.w;
            }
            s += __shfl_xor_sync(0xffffffffu, s, 1);
            s += __shfl_xor_sync(0xffffffffu, s, 2);
            s *= scale;
            if (spos[j] > pos_q) s = -1e30f;
            sc[j] = s;
            tmax = fmaxf(tmax, s);
        }

        float m_new = fmaxf(m, tmax);
        float corr  = __expf(m - m_new);
        l *= corr;
#pragma unroll
        for (int c = 0; c < 8; c++) {
            acc[c].x *= corr; acc[c].y *= corr;
            acc[c].z *= corr; acc[c].w *= corr;
        }
#pragma unroll
        for (int j = 0; j < 32; j++) {
            float p = __expf(sc[j] - m_new);
            l += p;
#pragma unroll
            for (int c0 = 0; c0 < 8; c0++) {
                int c = (c0 + 2 * sub) & 7;
                float4 v4 = Vs[j][sub * 8 + c];
                acc[c].x += p * v4.x; acc[c].y += p * v4.y;
                acc[c].z += p * v4.z; acc[c].w += p * v4.w;
            }
        }
        m = m_new;
    }

    float inv = 1.0f / l;
    float4* op = reinterpret_cast<float4*>(
        O + (size_t)(b * SEQ + sq) * QCOLS + h * 128 + sub * 32);
#pragma unroll
    for (int c = 0; c < 8; c++) {
        float4 v = acc[c];
        v.x *= inv; v.y *= inv; v.z *= inv; v.w *= inv;
        op[c] = v;
    }
}

// ---------------------------------------------------------------------------
// Launch: 5 warmups (ncu skip alignment) -> QKV -> RoPE -> attn -> Wo
// ---------------------------------------------------------------------------
extern "C" void kernel_launch(void* const* d_in, const int* in_sizes, int n_in,
                              void* d_out, int out_size)
{
    (void)in_sizes; (void)n_in; (void)out_size;
    const float* x    = (const float*)d_in[0];
    const int*   sidx = (const int*)  d_in[1];
    const float* Wq = (const float*)d_in[4];
    const float* bq = (const float*)d_in[5];
    const float* Wk = (const float*)d_in[6];
    const float* bk = (const float*)d_in[7];
    const float* Wv = (const float*)d_in[8];
    const float* bv = (const float*)d_in[9];
    const float* Wo = (const float*)d_in[10];
    float* out = (float*)d_out;

    float *pQ, *pK, *pV, *pAO;
    int* pD;
    cudaGetSymbolAddress((void**)&pQ,  g_Q);
    cudaGetSymbolAddress((void**)&pK,  g_K);
    cudaGetSymbolAddress((void**)&pV,  g_V);
    cudaGetSymbolAddress((void**)&pAO, g_AO);
    cudaGetSymbolAddress((void**)&pD,  g_dummy);

    // 5 dummy launches: ncu -s 5 -c 1 then captures the QKV GEMM.
    for (int i = 0; i < 5; i++) warm_kernel<<<1, 32>>>(pD);

    // QKV projections (+bias) — hybrid FFMA+HMMA
    sgemm_hybrid<<<dim3(QCOLS / 128, MROWS / 128), 512>>>(x, Wq, bq, pQ, MROWS, QCOLS, DMODEL);
    sgemm_hybrid<<<dim3(KCOLS / 128, MROWS / 128), 512>>>(x, Wk, bk, pK, MROWS, KCOLS, DMODEL);
    sgemm_hybrid<<<dim3(KCOLS / 128, MROWS / 128), 512>>>(x, Wv, bv, pV, MROWS, KCOLS, DMODEL);

    // RoPE on Q and K
    rope_kernel<<<(MROWS * NH   * 64 + 255) / 256, 256>>>(pQ, sidx, NH);
    rope_kernel<<<(MROWS * NKVH * 64 + 255) / 256, 256>>>(pK, sidx, NKVH);

    // Causal GQA flash attention
    attn_kernel<<<dim3(SEQ / 64, NH, BSZ), 256>>>(pQ, pK, pV, sidx, pAO);

    // Output projection
    sgemm_hybrid<<<dim3(DMODEL / 128, MROWS / 128), 512>>>(pAO, Wo, nullptr, out, MROWS, DMODEL, QCOLS);
}